// round 11
// baseline (speedup 1.0000x reference)
#include <cuda_runtime.h>
#include <cuda_bf16.h>
#include <cstdint>

#define U_    339
#define S_    5825
#define N_    6164
#define D_    128
#define H_    64
#define NNZ2_ 400000
#define B_    500000
#define EPS_  1e-5f

// ---------------- device scratch (static, no allocs) ----------------
__device__ int   g_cnt[N_];          // INVARIANT: zero at call entry (re-zeroed by scan)
__device__ int   g_cursor[N_];
__device__ int   g_rowptr[N_ + 1];
__device__ int   g_colidx[NNZ2_];
__device__ float g_vals[NNZ2_];
__device__ float g_Q[2 * 128 * 64];  // side0 = Qu (uH,W1top), side1 = Qi (iH,W1bot)
__device__ float g_P[N_ * H_];       // ping
__device__ float g_P2[N_ * H_];      // pong
__device__ float g_AB[N_ * H_];      // final: rows [0,U) have +b1

// ---------------- helpers ----------------
__device__ __forceinline__ uint32_t to_tf32(float f) {
    uint32_t r;
    asm("cvt.rna.tf32.f32 %0, %1;" : "=r"(r) : "f"(f));
    return r;
}
__device__ __forceinline__ void mma16n8k8(float c[4], uint32_t a0, uint32_t a1,
                                          uint32_t a2, uint32_t a3,
                                          uint32_t b0, uint32_t b1) {
    asm volatile(
        "mma.sync.aligned.m16n8k8.row.col.f32.tf32.tf32.f32 "
        "{%0,%1,%2,%3}, {%4,%5,%6,%7}, {%8,%9}, {%0,%1,%2,%3};"
        : "+f"(c[0]), "+f"(c[1]), "+f"(c[2]), "+f"(c[3])
        : "r"(a0), "r"(a1), "r"(a2), "r"(a3), "r"(b0), "r"(b1));
}

#define HB2 592
#define HT2 512
#define HCH ((NNZ2_ + HB2 - 1) / HB2)   // 676
#define SQ  2

// ---------------- K0: row histogram ----------------
__global__ void hist_kernel(const int* __restrict__ rows) {
    __shared__ int sc[N_];
    for (int t = threadIdx.x; t < N_; t += HT2) sc[t] = 0;
    __syncthreads();
    int start = blockIdx.x * HCH;
    int end = start + HCH; if (end > NNZ2_) end = NNZ2_;
    for (int i = start + threadIdx.x; i < end; i += HT2)
        atomicAdd(&sc[rows[i]], 1);
    __syncthreads();
    for (int t = threadIdx.x; t < N_; t += HT2) {
        int c = sc[t];
        if (c) atomicAdd(&g_cnt[t], c);
    }
}

// ---------------- K1: block0 = scan -> rowptr/cursor (+re-zero cnt); blocks1,2 = hyperQ ----------------
#define SCAN_CH 7
__global__ void scan_hyperQ_kernel(const float* __restrict__ uH, const float* __restrict__ iH,
                                   const float* __restrict__ W1) {
    int t = threadIdx.x;
    if (blockIdx.x == 0) {
        __shared__ int sh[1024];
        int base = t * SCAN_CH;
        int v[SCAN_CH];
        int s = 0;
#pragma unroll
        for (int q = 0; q < SCAN_CH; q++) {
            int idx = base + q;
            int c = 0;
            if (idx < N_) { c = g_cnt[idx]; g_cnt[idx] = 0; }
            v[q] = s;
            s += c;
        }
        sh[t] = s;
        __syncthreads();
        for (int off = 1; off < 1024; off <<= 1) {
            int add = (t >= off) ? sh[t - off] : 0;
            __syncthreads();
            sh[t] += add;
            __syncthreads();
        }
        int excl = (t == 0) ? 0 : sh[t - 1];
#pragma unroll
        for (int q = 0; q < SCAN_CH; q++) {
            int idx = base + q;
            if (idx < N_) {
                int p = excl + v[q];
                g_rowptr[idx] = p;
                g_cursor[idx] = p;
            }
        }
        if (t == 0) g_rowptr[N_] = NNZ2_;
    } else {
        int side = blockIdx.x - 1;
        const float* __restrict__ Hp = side ? iH : uH;
        const float* __restrict__ W1p = W1 + side * 128 * 64;
        __shared__ float sH[32 * 128];
        __shared__ float sRW[32 * 64];
        for (int i = t; i < 32 * 128; i += 1024) sH[i] = Hp[i];
        __syncthreads();
        for (int o = t; o < 32 * 64; o += 1024) {
            int r = o >> 6, j = o & 63;
            float acc = 0.f;
            for (int b = 0; b < 128; b++) acc += sH[r * 128 + b] * W1p[b * 64 + j];
            sRW[o] = acc;
        }
        __syncthreads();
        for (int o = t; o < 128 * 64; o += 1024) {
            int a = o >> 6, j = o & 63;
            float acc = 0.f;
#pragma unroll
            for (int r = 0; r < 32; r++) acc += sH[r * 128 + a] * sRW[r * 64 + j];
            g_Q[side * 128 * 64 + o] = acc;
        }
    }
}

// ---------------- K2: fused scatter (blocks [0,HB2)) + projB (blocks [HB2, HB2+PB)) ----------------
// projB: g_P[r] = e0[r] @ Q_swapped  (u-rows with Qi, s-rows with Qu), reading uE/iE directly.
#define PB ((N_ + 31) / 32)     // 193
__global__ void scatter_projB_kernel(const int* __restrict__ rows, const int* __restrict__ cols,
                                     const float* __restrict__ vals,
                                     const float* __restrict__ uE, const float* __restrict__ iE) {
    if (blockIdx.x < HB2) {
        __shared__ int sc[N_];
        for (int t = threadIdx.x; t < N_; t += HT2) sc[t] = 0;
        __syncthreads();
        int start = blockIdx.x * HCH;
        int end = start + HCH; if (end > NNZ2_) end = NNZ2_;

        int myrow[SQ], mycol[SQ], mypos[SQ];
        float myval[SQ];
#pragma unroll
        for (int q = 0; q < SQ; q++) {
            int i = start + q * HT2 + threadIdx.x;
            bool valid = (i < end);
            int r = valid ? rows[i] : 0;
            myrow[q] = valid ? r : -1;
            mycol[q] = valid ? cols[i] : 0;
            myval[q] = valid ? vals[i] : 0.f;
            mypos[q] = valid ? atomicAdd(&sc[r], 1) : 0;
        }
        __syncthreads();
        for (int t = threadIdx.x; t < N_; t += HT2) {
            int c = sc[t];
            if (c) sc[t] = atomicAdd(&g_cursor[t], c);
        }
        __syncthreads();
#pragma unroll
        for (int q = 0; q < SQ; q++) {
            if (myrow[q] >= 0) {
                int p = sc[myrow[q]] + mypos[q];
                g_colidx[p] = mycol[q];
                g_vals[p] = myval[q];
            }
        }
    } else {
        __shared__ float sE[32 * 128];
        int rb = (blockIdx.x - HB2) * 32;
        int tid = threadIdx.x;
        for (int t = tid; t < 32 * 128; t += HT2) {
            int r = rb + (t >> 7);
            float v = 0.f;
            if (r < U_) v = uE[r * 128 + (t & 127)];
            else if (r < N_) v = iE[(r - U_) * 128 + (t & 127)];
            sE[t] = v;
        }
        __syncthreads();
        int j = tid & 63;
        int rl0 = tid >> 6;     // 0..7
        for (int rl = rl0; rl < 32; rl += 8) {
            int r = rb + rl;
            if (r >= N_) break;
            const float* __restrict__ Qp = (r < U_) ? (g_Q + 128 * 64) : g_Q;  // u->Qi, s->Qu
            float acc = 0.f;
#pragma unroll 8
            for (int k = 0; k < 128; k++) acc += sE[rl * 128 + k] * Qp[k * 64 + j];
            g_P[r * 64 + j] = acc;
        }
    }
}

// ---------------- K3: 64-wide CSR SpMM, load-balanced, ping-pong ----------------
// mode 0: g_P -> g_P2 ; mode 1: g_P2 -> g_P ; mode 2: g_P -> g_AB (+b1 on u-rows)
#define SPMM_SBLKS ((S_ + 7) / 8)
__global__ void spmm64_kernel(int mode, const float* __restrict__ b1) {
    const float2* __restrict__ src = (mode == 1) ? (const float2*)g_P2 : (const float2*)g_P;
    float2* __restrict__ dst = (mode == 0) ? (float2*)g_P2
                              : (mode == 1 ? (float2*)g_P : (float2*)g_AB);
    int lane = threadIdx.x & 31;
    int w = threadIdx.x >> 5;

    if (blockIdx.x < U_) {
        int row = blockIdx.x;
        int beg = g_rowptr[row], end = g_rowptr[row + 1];
        float2 a = {0.f, 0.f};
        float2 a1 = {0.f, 0.f};
        int e = beg + w;
        for (; e + 8 < end; e += 16) {
            float v0 = g_vals[e];     int c0 = g_colidx[e];
            float v1 = g_vals[e + 8]; int c1 = g_colidx[e + 8];
            float2 t0 = src[c0 * 32 + lane];
            float2 t1 = src[c1 * 32 + lane];
            a.x += v0 * t0.x;  a.y += v0 * t0.y;
            a1.x += v1 * t1.x; a1.y += v1 * t1.y;
        }
        if (e < end) {
            float v = g_vals[e];
            int c = g_colidx[e];
            float2 t = src[c * 32 + lane];
            a.x += v * t.x; a.y += v * t.y;
        }
        a.x += a1.x; a.y += a1.y;
        __shared__ float2 red[256];
        int tid = threadIdx.x;
        red[tid] = a; __syncthreads();
        if (tid < 128) {
            float2 b = red[tid + 128];
            a.x += b.x; a.y += b.y;
            red[tid] = a;
        }
        __syncthreads();
        if (tid < 64) {
            float2 b = red[tid + 64];
            a.x += b.x; a.y += b.y;
            red[tid] = a;
        }
        __syncthreads();
        if (tid < 32) {
            float2 b = red[tid + 32];
            a.x += b.x; a.y += b.y;
            if (mode == 2) {
                a.x += b1[2 * lane];
                a.y += b1[2 * lane + 1];
            }
            dst[row * 32 + lane] = a;
        }
    } else {
        int row = U_ + (blockIdx.x - U_) * 8 + w;
        if (row >= N_) return;
        int beg = g_rowptr[row], end = g_rowptr[row + 1];
        float2 a0 = {0.f, 0.f};
        float2 a1 = {0.f, 0.f};
        float2 a2 = {0.f, 0.f};
        float2 a3 = {0.f, 0.f};
        int e = beg;
        for (; e + 4 <= end; e += 4) {
            float v0 = g_vals[e],     v1 = g_vals[e + 1];
            float v2 = g_vals[e + 2], v3 = g_vals[e + 3];
            int c0 = g_colidx[e],     c1 = g_colidx[e + 1];
            int c2 = g_colidx[e + 2], c3 = g_colidx[e + 3];
            float2 t0 = src[c0 * 32 + lane];
            float2 t1 = src[c1 * 32 + lane];
            float2 t2 = src[c2 * 32 + lane];
            float2 t3 = src[c3 * 32 + lane];
            a0.x += v0 * t0.x; a0.y += v0 * t0.y;
            a1.x += v1 * t1.x; a1.y += v1 * t1.y;
            a2.x += v2 * t2.x; a2.y += v2 * t2.y;
            a3.x += v3 * t3.x; a3.y += v3 * t3.y;
        }
        for (; e < end; e++) {
            float v0 = g_vals[e];
            int c0 = g_colidx[e];
            float2 t0 = src[c0 * 32 + lane];
            a0.x += v0 * t0.x; a0.y += v0 * t0.y;
        }
        a0.x += a1.x + a2.x + a3.x;
        a0.y += a1.y + a2.y + a3.y;
        dst[row * 32 + lane] = a0;
    }
}

// ---------------- K4: persistent fused MLP, layer-2 via mma.sync tf32 ----------------
#define XS 68
#define WS 72
#define NT_ ((B_ + 127) / 128)
#define MLP_GRID 592

__global__ void __launch_bounds__(128)
mlp_kernel(const int* __restrict__ uIdx, const int* __restrict__ sIdx,
           const float* __restrict__ g1, const float* __restrict__ be1,
           const float* __restrict__ W2, const float* __restrict__ b2,
           const float* __restrict__ g2, const float* __restrict__ be2,
           const float* __restrict__ W3, const float* __restrict__ b3,
           float* __restrict__ out) {
    extern __shared__ uint32_t sX[];          // [128 * XS]
    __shared__ uint32_t sW[64 * WS];
    __shared__ float4 sEp[64];
    __shared__ float sg1[64], sbe1[64];

    int tid = threadIdx.x;
    for (int idx = tid; idx < 64 * 64; idx += 128) {
        int k = idx >> 6, n = idx & 63;
        sW[k * WS + n] = to_tf32(W2[idx]);
    }
    if (tid < 64) {
        sg1[tid] = g1[tid]; sbe1[tid] = be1[tid];
        sEp[tid] = make_float4(b2[tid], g2[tid], be2[tid], W3[tid]);
    }
    __syncthreads();
    float bb = b3[0];

    int wid = tid >> 5;
    int lane = tid & 31;
    int gid = lane >> 2;
    int tig = lane & 3;
    uint32_t* rowp = sX + tid * XS;

    for (int tile = blockIdx.x; tile < NT_; tile += MLP_GRID) {
        int r = tile * 128 + tid;

        {
            float x[64];
            float sum = 0.f;
            if (r < B_) {
                int u = uIdx[r], s = sIdx[r];
                const float4* __restrict__ pa = (const float4*)(g_AB + u * H_);
                const float4* __restrict__ pb = (const float4*)(g_AB + (U_ + s) * H_);
#pragma unroll
                for (int q = 0; q < 16; q++) {
                    float4 a = pa[q];
                    float4 b = pb[q];
                    float v0 = a.x + b.x, v1 = a.y + b.y, v2 = a.z + b.z, v3 = a.w + b.w;
                    x[4 * q] = v0; x[4 * q + 1] = v1; x[4 * q + 2] = v2; x[4 * q + 3] = v3;
                    sum += v0 + v1 + v2 + v3;
                }
            } else {
#pragma unroll
                for (int k = 0; k < 64; k++) x[k] = 0.f;
            }
            float mu = sum * (1.f / 64.f);
            float var = 0.f;
#pragma unroll
            for (int k = 0; k < 64; k++) { float d = x[k] - mu; var += d * d; }
            float inv = rsqrtf(var * (1.f / 64.f) + EPS_);
#pragma unroll
            for (int q = 0; q < 16; q++) {
                uint4 w;
                w.x = to_tf32(fmaxf(0.f, (x[4 * q]     - mu) * inv * sg1[4 * q]     + sbe1[4 * q]));
                w.y = to_tf32(fmaxf(0.f, (x[4 * q + 1] - mu) * inv * sg1[4 * q + 1] + sbe1[4 * q + 1]));
                w.z = to_tf32(fmaxf(0.f, (x[4 * q + 2] - mu) * inv * sg1[4 * q + 2] + sbe1[4 * q + 2]));
                w.w = to_tf32(fmaxf(0.f, (x[4 * q + 3] - mu) * inv * sg1[4 * q + 3] + sbe1[4 * q + 3]));
                *(uint4*)(rowp + 4 * q) = w;
            }
        }
        __syncwarp();

#pragma unroll
        for (int mt = 0; mt < 2; mt++) {
            int mb = (wid * 2 + mt) * 16;
            const uint32_t* arow0 = sX + (mb + gid) * XS;
            const uint32_t* arow1 = sX + (mb + gid + 8) * XS;

            float c[8][4];
#pragma unroll
            for (int no = 0; no < 8; no++) {
                c[no][0] = 0.f; c[no][1] = 0.f; c[no][2] = 0.f; c[no][3] = 0.f;
            }
#pragma unroll
            for (int ko = 0; ko < 8; ko++) {
                int k0 = ko * 8;
                uint32_t a0 = arow0[k0 + tig];
                uint32_t a1 = arow1[k0 + tig];
                uint32_t a2 = arow0[k0 + tig + 4];
                uint32_t a3 = arow1[k0 + tig + 4];
                const uint32_t* bk0 = sW + (k0 + tig) * WS;
                const uint32_t* bk1 = sW + (k0 + tig + 4) * WS;
#pragma unroll
                for (int no = 0; no < 8; no++) {
                    uint32_t b0 = bk0[no * 8 + gid];
                    uint32_t b1 = bk1[no * 8 + gid];
                    mma16n8k8(c[no], a0, a1, a2, a3, b0, b1);
                }
            }

            float ep_g2[16], ep_be2[16], ep_w3[16];
            float s0 = 0.f, q0 = 0.f, s1 = 0.f, q1 = 0.f;
#pragma unroll
            for (int no = 0; no < 8; no++) {
                int col = no * 8 + 2 * tig;
                float4 e0 = sEp[col];
                float4 e1 = sEp[col + 1];
                ep_g2[2 * no] = e0.y;  ep_be2[2 * no] = e0.z;  ep_w3[2 * no] = e0.w;
                ep_g2[2 * no + 1] = e1.y; ep_be2[2 * no + 1] = e1.z; ep_w3[2 * no + 1] = e1.w;
                c[no][0] += e0.x; c[no][1] += e1.x;
                c[no][2] += e0.x; c[no][3] += e1.x;
                s0 += c[no][0] + c[no][1];
                q0 += c[no][0] * c[no][0] + c[no][1] * c[no][1];
                s1 += c[no][2] + c[no][3];
                q1 += c[no][2] * c[no][2] + c[no][3] * c[no][3];
            }
            s0 += __shfl_xor_sync(0xffffffffu, s0, 1);
            s0 += __shfl_xor_sync(0xffffffffu, s0, 2);
            q0 += __shfl_xor_sync(0xffffffffu, q0, 1);
            q0 += __shfl_xor_sync(0xffffffffu, q0, 2);
            s1 += __shfl_xor_sync(0xffffffffu, s1, 1);
            s1 += __shfl_xor_sync(0xffffffffu, s1, 2);
            q1 += __shfl_xor_sync(0xffffffffu, q1, 1);
            q1 += __shfl_xor_sync(0xffffffffu, q1, 2);

            float mu0 = s0 * (1.f / 64.f);
            float var0 = fmaxf(q0 * (1.f / 64.f) - mu0 * mu0, 0.f);
            float inv0 = rsqrtf(var0 + EPS_);
            float mu1 = s1 * (1.f / 64.f);
            float var1 = fmaxf(q1 * (1.f / 64.f) - mu1 * mu1, 0.f);
            float inv1 = rsqrtf(var1 + EPS_);

            float d0 = 0.f, d1 = 0.f;
#pragma unroll
            for (int no = 0; no < 8; no++) {
#pragma unroll
                for (int j = 0; j < 2; j++) {
                    int p = 2 * no + j;
                    float h0 = fmaxf(0.f, (c[no][j]     - mu0) * inv0 * ep_g2[p] + ep_be2[p]);
                    float h1 = fmaxf(0.f, (c[no][2 + j] - mu1) * inv1 * ep_g2[p] + ep_be2[p]);
                    d0 += h0 * ep_w3[p];
                    d1 += h1 * ep_w3[p];
                }
            }
            d0 += __shfl_xor_sync(0xffffffffu, d0, 1);
            d0 += __shfl_xor_sync(0xffffffffu, d0, 2);
            d1 += __shfl_xor_sync(0xffffffffu, d1, 1);
            d1 += __shfl_xor_sync(0xffffffffu, d1, 2);

            if (tig == 0) {
                int r0 = tile * 128 + mb + gid;
                int r1 = r0 + 8;
                if (r0 < B_) out[r0] = d0 + bb;
                if (r1 < B_) out[r1] = d1 + bb;
            }
        }
        __syncwarp();
    }
}

// ---------------- launcher ----------------
extern "C" void kernel_launch(void* const* d_in, const int* in_sizes, int n_in,
                              void* d_out, int out_size) {
    const float* uE  = (const float*)d_in[0];
    const float* iE  = (const float*)d_in[1];
    const float* uH  = (const float*)d_in[2];
    const float* iH  = (const float*)d_in[3];
    const float* W1  = (const float*)d_in[4];
    const float* b1  = (const float*)d_in[5];
    const float* g1  = (const float*)d_in[6];
    const float* be1 = (const float*)d_in[7];
    const float* W2  = (const float*)d_in[8];
    const float* b2  = (const float*)d_in[9];
    const float* g2  = (const float*)d_in[10];
    const float* be2 = (const float*)d_in[11];
    const float* W3  = (const float*)d_in[12];
    const float* b3  = (const float*)d_in[13];
    const float* adj_vals = (const float*)d_in[14];
    const int*   adj_rows = (const int*)d_in[15];
    const int*   adj_cols = (const int*)d_in[16];
    const int*   uIdx = (const int*)d_in[17];
    const int*   sIdx = (const int*)d_in[18];
    float* out = (float*)d_out;

    static int attr_set = 0;
    if (!attr_set) {
        cudaFuncSetAttribute(mlp_kernel, cudaFuncAttributeMaxDynamicSharedMemorySize,
                             128 * XS * 4);
        attr_set = 1;
    }

    hist_kernel<<<HB2, HT2>>>(adj_rows);
    scan_hyperQ_kernel<<<3, 1024>>>(uH, iH, W1);
    scatter_projB_kernel<<<HB2 + PB, HT2>>>(adj_rows, adj_cols, adj_vals, uE, iE);
    spmm64_kernel<<<U_ + SPMM_SBLKS, 256>>>(0, b1);   // c = A b
    spmm64_kernel<<<U_ + SPMM_SBLKS, 256>>>(1, b1);   // d = A c
    spmm64_kernel<<<U_ + SPMM_SBLKS, 256>>>(2, b1);   // AB = A d (+b1)
    mlp_kernel<<<MLP_GRID, 128, 128 * XS * 4>>>(uIdx, sIdx, g1, be1, W2, b2,
                                                g2, be2, W3, b3, out);
}

// round 13
// speedup vs baseline: 1.0614x; 1.0614x over previous
#include <cuda_runtime.h>
#include <cuda_bf16.h>
#include <cstdint>

#define U_    339
#define S_    5825
#define N_    6164
#define D_    128
#define H_    64
#define NNZ2_ 400000
#define B_    500000
#define EPS_  1e-5f

// ---------------- device scratch (static, no allocs) ----------------
__device__ int   g_cnt[N_];          // INVARIANT: zero at call entry (re-zeroed by scan)
__device__ int   g_cursor[N_];
__device__ int   g_rowptr[N_ + 1];
__device__ int   g_colidx[NNZ2_];
__device__ float g_vals[NNZ2_];
__device__ float g_Q[2 * 128 * 64];  // side0 = Qu (uH,W1top), side1 = Qi (iH,W1bot)
__device__ float g_P[N_ * H_];       // ping
__device__ float g_P2[N_ * H_];      // pong
__device__ float g_AB[N_ * H_];      // final: rows [0,U) have +b1

// ---------------- helpers ----------------
__device__ __forceinline__ uint32_t to_tf32(float f) {
    uint32_t r;
    asm("cvt.rna.tf32.f32 %0, %1;" : "=r"(r) : "f"(f));
    return r;
}
__device__ __forceinline__ void mma16n8k8(float c[4], uint32_t a0, uint32_t a1,
                                          uint32_t a2, uint32_t a3,
                                          uint32_t b0, uint32_t b1) {
    asm volatile(
        "mma.sync.aligned.m16n8k8.row.col.f32.tf32.tf32.f32 "
        "{%0,%1,%2,%3}, {%4,%5,%6,%7}, {%8,%9}, {%0,%1,%2,%3};"
        : "+f"(c[0]), "+f"(c[1]), "+f"(c[2]), "+f"(c[3])
        : "r"(a0), "r"(a1), "r"(a2), "r"(a3), "r"(b0), "r"(b1));
}

#define HB2 592
#define HT2 512
#define HCH ((NNZ2_ + HB2 - 1) / HB2)   // 676
#define SQ  2

// ---------------- K0: row histogram ----------------
__global__ void hist_kernel(const int* __restrict__ rows) {
    __shared__ int sc[N_];
    for (int t = threadIdx.x; t < N_; t += HT2) sc[t] = 0;
    __syncthreads();
    int start = blockIdx.x * HCH;
    int end = start + HCH; if (end > NNZ2_) end = NNZ2_;
    for (int i = start + threadIdx.x; i < end; i += HT2)
        atomicAdd(&sc[rows[i]], 1);
    __syncthreads();
    for (int t = threadIdx.x; t < N_; t += HT2) {
        int c = sc[t];
        if (c) atomicAdd(&g_cnt[t], c);
    }
}

// ---------------- K1: block0 = scan -> rowptr/cursor (+re-zero cnt); blocks1,2 = hyperQ ----------------
#define SCAN_CH 7
__global__ void scan_hyperQ_kernel(const float* __restrict__ uH, const float* __restrict__ iH,
                                   const float* __restrict__ W1) {
    int t = threadIdx.x;
    if (blockIdx.x == 0) {
        __shared__ int sh[1024];
        int base = t * SCAN_CH;
        int v[SCAN_CH];
        int s = 0;
#pragma unroll
        for (int q = 0; q < SCAN_CH; q++) {
            int idx = base + q;
            int c = 0;
            if (idx < N_) { c = g_cnt[idx]; g_cnt[idx] = 0; }
            v[q] = s;
            s += c;
        }
        sh[t] = s;
        __syncthreads();
        for (int off = 1; off < 1024; off <<= 1) {
            int add = (t >= off) ? sh[t - off] : 0;
            __syncthreads();
            sh[t] += add;
            __syncthreads();
        }
        int excl = (t == 0) ? 0 : sh[t - 1];
#pragma unroll
        for (int q = 0; q < SCAN_CH; q++) {
            int idx = base + q;
            if (idx < N_) {
                int p = excl + v[q];
                g_rowptr[idx] = p;
                g_cursor[idx] = p;
            }
        }
        if (t == 0) g_rowptr[N_] = NNZ2_;
    } else {
        int side = blockIdx.x - 1;
        const float* __restrict__ Hp = side ? iH : uH;
        const float* __restrict__ W1p = W1 + side * 128 * 64;
        __shared__ float sH[32 * 128];
        __shared__ float sRW[32 * 64];
        for (int i = t; i < 32 * 128; i += 1024) sH[i] = Hp[i];
        __syncthreads();
        for (int o = t; o < 32 * 64; o += 1024) {
            int r = o >> 6, j = o & 63;
            float acc = 0.f;
            for (int b = 0; b < 128; b++) acc += sH[r * 128 + b] * W1p[b * 64 + j];
            sRW[o] = acc;
        }
        __syncthreads();
        for (int o = t; o < 128 * 64; o += 1024) {
            int a = o >> 6, j = o & 63;
            float acc = 0.f;
#pragma unroll
            for (int r = 0; r < 32; r++) acc += sH[r * 128 + a] * sRW[r * 64 + j];
            g_Q[side * 128 * 64 + o] = acc;
        }
    }
}

// ---------------- K2: fused scatter (blocks [0,HB2)) + projB (blocks [HB2, HB2+PB)) ----------------
#define PB ((N_ + 31) / 32)     // 193
__global__ void scatter_projB_kernel(const int* __restrict__ rows, const int* __restrict__ cols,
                                     const float* __restrict__ vals,
                                     const float* __restrict__ uE, const float* __restrict__ iE) {
    if (blockIdx.x < HB2) {
        __shared__ int sc[N_];
        for (int t = threadIdx.x; t < N_; t += HT2) sc[t] = 0;
        __syncthreads();
        int start = blockIdx.x * HCH;
        int end = start + HCH; if (end > NNZ2_) end = NNZ2_;

        int myrow[SQ], mycol[SQ], mypos[SQ];
        float myval[SQ];
#pragma unroll
        for (int q = 0; q < SQ; q++) {
            int i = start + q * HT2 + threadIdx.x;
            bool valid = (i < end);
            int r = valid ? rows[i] : 0;
            myrow[q] = valid ? r : -1;
            mycol[q] = valid ? cols[i] : 0;
            myval[q] = valid ? vals[i] : 0.f;
            mypos[q] = valid ? atomicAdd(&sc[r], 1) : 0;
        }
        __syncthreads();
        for (int t = threadIdx.x; t < N_; t += HT2) {
            int c = sc[t];
            if (c) sc[t] = atomicAdd(&g_cursor[t], c);
        }
        __syncthreads();
#pragma unroll
        for (int q = 0; q < SQ; q++) {
            if (myrow[q] >= 0) {
                int p = sc[myrow[q]] + mypos[q];
                g_colidx[p] = mycol[q];
                g_vals[p] = myval[q];
            }
        }
    } else {
        __shared__ float sE[32 * 128];
        int rb = (blockIdx.x - HB2) * 32;
        int tid = threadIdx.x;
        for (int t = tid; t < 32 * 128; t += HT2) {
            int r = rb + (t >> 7);
            float v = 0.f;
            if (r < U_) v = uE[r * 128 + (t & 127)];
            else if (r < N_) v = iE[(r - U_) * 128 + (t & 127)];
            sE[t] = v;
        }
        __syncthreads();
        int j = tid & 63;
        int rl0 = tid >> 6;     // 0..7
        for (int rl = rl0; rl < 32; rl += 8) {
            int r = rb + rl;
            if (r >= N_) break;
            const float* __restrict__ Qp = (r < U_) ? (g_Q + 128 * 64) : g_Q;  // u->Qi, s->Qu
            float acc = 0.f;
#pragma unroll 8
            for (int k = 0; k < 128; k++) acc += sE[rl * 128 + k] * Qp[k * 64 + j];
            g_P[r * 64 + j] = acc;
        }
    }
}

// ---------------- K3: 64-wide CSR SpMM, software-pipelined batch-8 gathers ----------------
// mode 0: g_P -> g_P2 ; mode 1: g_P2 -> g_P ; mode 2: g_P -> g_AB (+b1 on u-rows)
#define SPMM_SBLKS ((S_ + 7) / 8)
__global__ void __launch_bounds__(256) spmm64_kernel(int mode, const float* __restrict__ b1) {
    const float2* __restrict__ src = (mode == 1) ? (const float2*)g_P2 : (const float2*)g_P;
    float2* __restrict__ dst = (mode == 0) ? (float2*)g_P2
                              : (mode == 1 ? (float2*)g_P : (float2*)g_AB);
    int lane = threadIdx.x & 31;
    int w = threadIdx.x >> 5;

    bool urow = (blockIdx.x < U_);
    int row, e, end, stride;
    if (urow) {
        row = blockIdx.x;
        e = g_rowptr[row] + w;
        end = g_rowptr[row + 1];
        stride = 8;
    } else {
        row = U_ + (blockIdx.x - U_) * 8 + w;
        if (row >= N_) return;
        e = g_rowptr[row];
        end = g_rowptr[row + 1];
        stride = 1;
    }

    // 4 rotating accumulators; batch of 8 edges: 8 independent index loads,
    // then 8 independent gathers -> deep MLP, shallow dependency chain.
    float2 a0 = {0.f, 0.f}, a1 = {0.f, 0.f}, a2 = {0.f, 0.f}, a3 = {0.f, 0.f};
    for (; e + 7 * stride < end; e += 8 * stride) {
        int c0 = g_colidx[e];
        int c1 = g_colidx[e + stride];
        int c2 = g_colidx[e + 2 * stride];
        int c3 = g_colidx[e + 3 * stride];
        int c4 = g_colidx[e + 4 * stride];
        int c5 = g_colidx[e + 5 * stride];
        int c6 = g_colidx[e + 6 * stride];
        int c7 = g_colidx[e + 7 * stride];
        float v0 = g_vals[e];
        float v1 = g_vals[e + stride];
        float v2 = g_vals[e + 2 * stride];
        float v3 = g_vals[e + 3 * stride];
        float v4 = g_vals[e + 4 * stride];
        float v5 = g_vals[e + 5 * stride];
        float v6 = g_vals[e + 6 * stride];
        float v7 = g_vals[e + 7 * stride];
        float2 t0 = src[c0 * 32 + lane];
        float2 t1 = src[c1 * 32 + lane];
        float2 t2 = src[c2 * 32 + lane];
        float2 t3 = src[c3 * 32 + lane];
        float2 t4 = src[c4 * 32 + lane];
        float2 t5 = src[c5 * 32 + lane];
        float2 t6 = src[c6 * 32 + lane];
        float2 t7 = src[c7 * 32 + lane];
        a0.x += v0 * t0.x; a0.y += v0 * t0.y;
        a1.x += v1 * t1.x; a1.y += v1 * t1.y;
        a2.x += v2 * t2.x; a2.y += v2 * t2.y;
        a3.x += v3 * t3.x; a3.y += v3 * t3.y;
        a0.x += v4 * t4.x; a0.y += v4 * t4.y;
        a1.x += v5 * t5.x; a1.y += v5 * t5.y;
        a2.x += v6 * t6.x; a2.y += v6 * t6.y;
        a3.x += v7 * t7.x; a3.y += v7 * t7.y;
    }
    // tail (<8 edges): still batch the index loads
    {
        int c[7]; float v[7];
        int cnt = 0;
        for (int ee = e; ee < end; ee += stride) {
            c[cnt] = g_colidx[ee];
            v[cnt] = g_vals[ee];
            cnt++;
        }
        for (int q = 0; q < cnt; q++) {
            float2 t = src[c[q] * 32 + lane];
            a0.x += v[q] * t.x; a0.y += v[q] * t.y;
        }
    }
    float2 a;
    a.x = (a0.x + a1.x) + (a2.x + a3.x);
    a.y = (a0.y + a1.y) + (a2.y + a3.y);

    if (!urow) {
        dst[row * 32 + lane] = a;
        return;
    }
    // u-row: reduce 8 warps
    __shared__ float2 red[256];
    int tid = threadIdx.x;
    red[tid] = a; __syncthreads();
    if (tid < 128) {
        float2 b = red[tid + 128];
        a.x += b.x; a.y += b.y;
        red[tid] = a;
    }
    __syncthreads();
    if (tid < 64) {
        float2 b = red[tid + 64];
        a.x += b.x; a.y += b.y;
        red[tid] = a;
    }
    __syncthreads();
    if (tid < 32) {
        float2 b = red[tid + 32];
        a.x += b.x; a.y += b.y;
        if (mode == 2) {
            a.x += b1[2 * lane];
            a.y += b1[2 * lane + 1];
        }
        dst[row * 32 + lane] = a;
    }
}

// ---------------- K4: persistent fused MLP, layer-2 via mma.sync tf32 ----------------
#define XS 68
#define WS 72
#define NT_ ((B_ + 127) / 128)
#define MLP_GRID 592

__global__ void __launch_bounds__(128)
mlp_kernel(const int* __restrict__ uIdx, const int* __restrict__ sIdx,
           const float* __restrict__ g1, const float* __restrict__ be1,
           const float* __restrict__ W2, const float* __restrict__ b2,
           const float* __restrict__ g2, const float* __restrict__ be2,
           const float* __restrict__ W3, const float* __restrict__ b3,
           float* __restrict__ out) {
    extern __shared__ uint32_t sX[];          // [128 * XS]
    __shared__ uint32_t sW[64 * WS];
    __shared__ float4 sEp[64];
    __shared__ float sg1[64], sbe1[64];

    int tid = threadIdx.x;
    for (int idx = tid; idx < 64 * 64; idx += 128) {
        int k = idx >> 6, n = idx & 63;
        sW[k * WS + n] = to_tf32(W2[idx]);
    }
    if (tid < 64) {
        sg1[tid] = g1[tid]; sbe1[tid] = be1[tid];
        sEp[tid] = make_float4(b2[tid], g2[tid], be2[tid], W3[tid]);
    }
    __syncthreads();
    float bb = b3[0];

    int wid = tid >> 5;
    int lane = tid & 31;
    int gid = lane >> 2;
    int tig = lane & 3;
    uint32_t* rowp = sX + tid * XS;

    for (int tile = blockIdx.x; tile < NT_; tile += MLP_GRID) {
        int r = tile * 128 + tid;

        {
            float x[64];
            float sum = 0.f;
            if (r < B_) {
                int u = uIdx[r], s = sIdx[r];
                const float4* __restrict__ pa = (const float4*)(g_AB + u * H_);
                const float4* __restrict__ pb = (const float4*)(g_AB + (U_ + s) * H_);
#pragma unroll
                for (int q = 0; q < 16; q++) {
                    float4 a = pa[q];
                    float4 b = pb[q];
                    float v0 = a.x + b.x, v1 = a.y + b.y, v2 = a.z + b.z, v3 = a.w + b.w;
                    x[4 * q] = v0; x[4 * q + 1] = v1; x[4 * q + 2] = v2; x[4 * q + 3] = v3;
                    sum += v0 + v1 + v2 + v3;
                }
            } else {
#pragma unroll
                for (int k = 0; k < 64; k++) x[k] = 0.f;
            }
            float mu = sum * (1.f / 64.f);
            float var = 0.f;
#pragma unroll
            for (int k = 0; k < 64; k++) { float d = x[k] - mu; var += d * d; }
            float inv = rsqrtf(var * (1.f / 64.f) + EPS_);
#pragma unroll
            for (int q = 0; q < 16; q++) {
                uint4 w;
                w.x = to_tf32(fmaxf(0.f, (x[4 * q]     - mu) * inv * sg1[4 * q]     + sbe1[4 * q]));
                w.y = to_tf32(fmaxf(0.f, (x[4 * q + 1] - mu) * inv * sg1[4 * q + 1] + sbe1[4 * q + 1]));
                w.z = to_tf32(fmaxf(0.f, (x[4 * q + 2] - mu) * inv * sg1[4 * q + 2] + sbe1[4 * q + 2]));
                w.w = to_tf32(fmaxf(0.f, (x[4 * q + 3] - mu) * inv * sg1[4 * q + 3] + sbe1[4 * q + 3]));
                *(uint4*)(rowp + 4 * q) = w;
            }
        }
        __syncwarp();

#pragma unroll
        for (int mt = 0; mt < 2; mt++) {
            int mb = (wid * 2 + mt) * 16;
            const uint32_t* arow0 = sX + (mb + gid) * XS;
            const uint32_t* arow1 = sX + (mb + gid + 8) * XS;

            float c[8][4];
#pragma unroll
            for (int no = 0; no < 8; no++) {
                c[no][0] = 0.f; c[no][1] = 0.f; c[no][2] = 0.f; c[no][3] = 0.f;
            }
#pragma unroll
            for (int ko = 0; ko < 8; ko++) {
                int k0 = ko * 8;
                uint32_t a0 = arow0[k0 + tig];
                uint32_t a1 = arow1[k0 + tig];
                uint32_t a2 = arow0[k0 + tig + 4];
                uint32_t a3 = arow1[k0 + tig + 4];
                const uint32_t* bk0 = sW + (k0 + tig) * WS;
                const uint32_t* bk1 = sW + (k0 + tig + 4) * WS;
#pragma unroll
                for (int no = 0; no < 8; no++) {
                    uint32_t b0 = bk0[no * 8 + gid];
                    uint32_t b1 = bk1[no * 8 + gid];
                    mma16n8k8(c[no], a0, a1, a2, a3, b0, b1);
                }
            }

            float ep_g2[16], ep_be2[16], ep_w3[16];
            float s0 = 0.f, q0 = 0.f, s1 = 0.f, q1 = 0.f;
#pragma unroll
            for (int no = 0; no < 8; no++) {
                int col = no * 8 + 2 * tig;
                float4 e0 = sEp[col];
                float4 e1 = sEp[col + 1];
                ep_g2[2 * no] = e0.y;  ep_be2[2 * no] = e0.z;  ep_w3[2 * no] = e0.w;
                ep_g2[2 * no + 1] = e1.y; ep_be2[2 * no + 1] = e1.z; ep_w3[2 * no + 1] = e1.w;
                c[no][0] += e0.x; c[no][1] += e1.x;
                c[no][2] += e0.x; c[no][3] += e1.x;
                s0 += c[no][0] + c[no][1];
                q0 += c[no][0] * c[no][0] + c[no][1] * c[no][1];
                s1 += c[no][2] + c[no][3];
                q1 += c[no][2] * c[no][2] + c[no][3] * c[no][3];
            }
            s0 += __shfl_xor_sync(0xffffffffu, s0, 1);
            s0 += __shfl_xor_sync(0xffffffffu, s0, 2);
            q0 += __shfl_xor_sync(0xffffffffu, q0, 1);
            q0 += __shfl_xor_sync(0xffffffffu, q0, 2);
            s1 += __shfl_xor_sync(0xffffffffu, s1, 1);
            s1 += __shfl_xor_sync(0xffffffffu, s1, 2);
            q1 += __shfl_xor_sync(0xffffffffu, q1, 1);
            q1 += __shfl_xor_sync(0xffffffffu, q1, 2);

            float mu0 = s0 * (1.f / 64.f);
            float var0 = fmaxf(q0 * (1.f / 64.f) - mu0 * mu0, 0.f);
            float inv0 = rsqrtf(var0 + EPS_);
            float mu1 = s1 * (1.f / 64.f);
            float var1 = fmaxf(q1 * (1.f / 64.f) - mu1 * mu1, 0.f);
            float inv1 = rsqrtf(var1 + EPS_);

            float d0 = 0.f, d1 = 0.f;
#pragma unroll
            for (int no = 0; no < 8; no++) {
#pragma unroll
                for (int j = 0; j < 2; j++) {
                    int p = 2 * no + j;
                    float h0 = fmaxf(0.f, (c[no][j]     - mu0) * inv0 * ep_g2[p] + ep_be2[p]);
                    float h1 = fmaxf(0.f, (c[no][2 + j] - mu1) * inv1 * ep_g2[p] + ep_be2[p]);
                    d0 += h0 * ep_w3[p];
                    d1 += h1 * ep_w3[p];
                }
            }
            d0 += __shfl_xor_sync(0xffffffffu, d0, 1);
            d0 += __shfl_xor_sync(0xffffffffu, d0, 2);
            d1 += __shfl_xor_sync(0xffffffffu, d1, 1);
            d1 += __shfl_xor_sync(0xffffffffu, d1, 2);

            if (tig == 0) {
                int r0 = tile * 128 + mb + gid;
                int r1 = r0 + 8;
                if (r0 < B_) out[r0] = d0 + bb;
                if (r1 < B_) out[r1] = d1 + bb;
            }
        }
        __syncwarp();
    }
}

// ---------------- launcher ----------------
extern "C" void kernel_launch(void* const* d_in, const int* in_sizes, int n_in,
                              void* d_out, int out_size) {
    const float* uE  = (const float*)d_in[0];
    const float* iE  = (const float*)d_in[1];
    const float* uH  = (const float*)d_in[2];
    const float* iH  = (const float*)d_in[3];
    const float* W1  = (const float*)d_in[4];
    const float* b1  = (const float*)d_in[5];
    const float* g1  = (const float*)d_in[6];
    const float* be1 = (const float*)d_in[7];
    const float* W2  = (const float*)d_in[8];
    const float* b2  = (const float*)d_in[9];
    const float* g2  = (const float*)d_in[10];
    const float* be2 = (const float*)d_in[11];
    const float* W3  = (const float*)d_in[12];
    const float* b3  = (const float*)d_in[13];
    const float* adj_vals = (const float*)d_in[14];
    const int*   adj_rows = (const int*)d_in[15];
    const int*   adj_cols = (const int*)d_in[16];
    const int*   uIdx = (const int*)d_in[17];
    const int*   sIdx = (const int*)d_in[18];
    float* out = (float*)d_out;

    static int attr_set = 0;
    if (!attr_set) {
        cudaFuncSetAttribute(mlp_kernel, cudaFuncAttributeMaxDynamicSharedMemorySize,
                             128 * XS * 4);
        attr_set = 1;
    }

    hist_kernel<<<HB2, HT2>>>(adj_rows);
    scan_hyperQ_kernel<<<3, 1024>>>(uH, iH, W1);
    scatter_projB_kernel<<<HB2 + PB, HT2>>>(adj_rows, adj_cols, adj_vals, uE, iE);
    spmm64_kernel<<<U_ + SPMM_SBLKS, 256>>>(0, b1);   // c = A b
    spmm64_kernel<<<U_ + SPMM_SBLKS, 256>>>(1, b1);   // d = A c
    spmm64_kernel<<<U_ + SPMM_SBLKS, 256>>>(2, b1);   // AB = A d (+b1)
    mlp_kernel<<<MLP_GRID, 128, 128 * XS * 4>>>(uIdx, sIdx, g1, be1, W2, b2,
                                                g2, be2, W3, b3, out);
}